// round 16
// baseline (speedup 1.0000x reference)
#include <cuda_runtime.h>
#include <cuda_fp16.h>
#include <math.h>
#include <stdint.h>

#define B_   2
#define S_   1024
#define D_   768
#define H_   12
#define DFF_ 3072
#define BS_  2048
#define MREL 131072
#define STAGES 4

// ---------------- scratch ----------------
__device__ float  g_x1 [BS_*D_];
__device__ float  g_A  [BS_*D_];
__device__ float  g_Bm [BS_*D_];
__device__ float  g_x2 [BS_*D_];
__device__ __half g_Hp [(size_t)MREL*D_];   // relation out fp16; also fp32 split-K scratch
__device__ __half g_G  [(size_t)MREL*D_];
__device__ __half g_hh [BS_*D_];
__device__ __half g_qh [BS_*D_];
__device__ __half g_kh [BS_*D_];
__device__ __half g_vh [BS_*D_];
__device__ __half g_ctxh[BS_*D_];
__device__ __half g_x1h[BS_*D_];
__device__ __half g_fh [BS_*DFF_];
// fp16 weights
__device__ __half g_Wqh[D_*D_], g_Wkh[D_*D_], g_Wvh[D_*D_], g_Woh[D_*D_];
__device__ __half g_W1h[2*D_*D_], g_W2h[D_*D_];
__device__ __half g_E1h[D_*DFF_], g_E2h[DFF_*D_];

__device__ __forceinline__ float gelu_f(float x) {
    return 0.5f * x * (1.0f + erff(x * 0.70710678118654752f));
}
__device__ __forceinline__ uint32_t smem_u32(const void* p) {
    return (uint32_t)__cvta_generic_to_shared(p);
}
__device__ __forceinline__ void cp16(uint32_t dst, const void* src, bool pred) {
    int sz = pred ? 16 : 0;
    asm volatile("cp.async.cg.shared.global [%0], [%1], 16, %2;\n"
                 :: "r"(dst), "l"(src), "r"(sz));
}
#define CP_COMMIT() asm volatile("cp.async.commit_group;\n")
#define CP_WAIT(n)  asm volatile("cp.async.wait_group %0;\n" :: "n"(n))

__device__ __forceinline__ void ldm_x4(uint32_t* r, uint32_t a) {
    asm volatile("ldmatrix.sync.aligned.m8n8.x4.shared.b16 {%0,%1,%2,%3},[%4];"
                 : "=r"(r[0]), "=r"(r[1]), "=r"(r[2]), "=r"(r[3]) : "r"(a));
}
__device__ __forceinline__ void ldm_x2t(uint32_t* r, uint32_t a) {
    asm volatile("ldmatrix.sync.aligned.m8n8.x2.trans.shared.b16 {%0,%1},[%2];"
                 : "=r"(r[0]), "=r"(r[1]) : "r"(a));
}
__device__ __forceinline__ void ldm_x2(uint32_t* r, uint32_t a) {
    asm volatile("ldmatrix.sync.aligned.m8n8.x2.shared.b16 {%0,%1},[%2];"
                 : "=r"(r[0]), "=r"(r[1]) : "r"(a));
}
__device__ __forceinline__ void mma_h(float* c, const uint32_t* a, const uint32_t* b) {
    asm volatile(
        "mma.sync.aligned.m16n8k16.row.col.f32.f16.f16.f32 "
        "{%0,%1,%2,%3},{%4,%5,%6,%7},{%8,%9},{%0,%1,%2,%3};\n"
        : "+f"(c[0]), "+f"(c[1]), "+f"(c[2]), "+f"(c[3])
        : "r"(a[0]), "r"(a[1]), "r"(a[2]), "r"(a[3]), "r"(b[0]), "r"(b[1]));
}

// -------- conflict-free swizzled smem offsets (in halves) --------
__device__ __forceinline__ int swzA(int row, int kc) {
    int idx = 2*row + kc;
    int L = idx >> 3;
    return (L << 6) + ((((idx & 7) ^ (L & 7))) << 3);
}
__device__ __forceinline__ int swzB(int k, int cc) {
    return ((2*k + (cc >> 3)) << 6) + (((cc & 7) ^ (k & 7)) << 3);
}
__device__ __forceinline__ int swz64(int row, int c) {
    return (row << 6) + (((c ^ (row & 7))) << 3);
}

// ---------------- fused fp32 -> fp16 conversion over 8 segments ----------------
struct ConvP {
    const float* src[8];
    __half* dst[8];
    int off[9];
};
__global__ void conv_all(ConvP p) {
    int e = (blockIdx.x * 256 + threadIdx.x) * 4;
    if (e >= p.off[8]) return;
    int s = 0;
#pragma unroll
    for (int k = 0; k < 7; k++) s += (e >= p.off[k+1]);
    int le = e - p.off[s];
    float4 v = *(const float4*)(p.src[s] + le);
    __half2 a = __floats2half2_rn(v.x, v.y);
    __half2 b = __floats2half2_rn(v.z, v.w);
    *(uint2*)(p.dst[s] + le) = make_uint2(*(uint32_t*)&a, *(uint32_t*)&b);
}

// ---------------- G = gelu(A_i + B_j) materialization (fp16) ----------------
__global__ void __launch_bounds__(192)
gelu_mat(const float* __restrict__ A, const float* __restrict__ Bm,
         __half* __restrict__ G) {
    const int bx = blockIdx.x, jh = blockIdx.y, t = threadIdx.x;
    const int cb = (bx >> 6) << 6;
    const int i  = bx & 63;
    float4 a = *(const float4*)(A + (size_t)(cb + i) * D_ + t*4);
    const float* Bbase = Bm + (size_t)cb * D_ + t*4;
    __half* Gb = G + (size_t)bx * 64 * D_ + t*4;
#pragma unroll 4
    for (int j = jh*32; j < jh*32 + 32; j++) {
        float4 b = *(const float4*)(Bbase + (size_t)j * D_);
        __half2 h0 = __floats2half2_rn(gelu_f(a.x+b.x), gelu_f(a.y+b.y));
        __half2 h1 = __floats2half2_rn(gelu_f(a.z+b.z), gelu_f(a.w+b.w));
        *(uint2*)(Gb + (size_t)j * D_) = make_uint2(*(uint32_t*)&h0, *(uint32_t*)&h1);
    }
}

// ================== flash attention (register-resident P) ==========
#define FQ_ST 8192
#define FKV_ST 4096
__global__ void __launch_bounds__(256, 2)
flash_attn(const __half* __restrict__ Q, const __half* __restrict__ K,
           const __half* __restrict__ V, __half* __restrict__ O) {
    extern __shared__ __align__(16) __half sm[];
    __half* Qs = sm;
    __half* Ks = sm + FQ_ST;
    __half* Vs = sm + FQ_ST + 2*FKV_ST;

    const int t = threadIdx.x, qt = blockIdx.x, bh = blockIdx.y;
    const int b = bh / H_, h = bh % H_;
    const int lane = t & 31, wid = t >> 5;
    const int g = lane >> 2, tg = lane & 3;
    const int l16 = lane & 15, lhi = lane >> 4;

    const __half* Qg = Q + (size_t)b * S_ * D_ + h * 64;
    const __half* Kg = K + (size_t)b * S_ * D_ + h * 64;
    const __half* Vg = V + (size_t)b * S_ * D_ + h * 64;

    auto loadQ = [&]() {
#pragma unroll
        for (int i = 0; i < 4; i++) {
            int cid = t + i*256;
            int r = cid >> 3, c = cid & 7;
            cp16(smem_u32(Qs + swz64(r, c)),
                 Qg + (size_t)(qt*128 + r) * D_ + c*8, true);
        }
    };
    auto loadKV = [&](int st, int kt) {
#pragma unroll
        for (int i = 0; i < 2; i++) {
            int cid = t + i*256;
            int r = cid >> 3, c = cid & 7;
            cp16(smem_u32(Ks + st*FKV_ST + swz64(r, c)),
                 Kg + (size_t)(kt*64 + r) * D_ + c*8, true);
        }
#pragma unroll
        for (int i = 0; i < 2; i++) {
            int cid = t + i*256;
            int r = cid >> 3, c = cid & 7;
            cp16(smem_u32(Vs + st*FKV_ST + swz64(r, c)),
                 Vg + (size_t)(kt*64 + r) * D_ + c*8, true);
        }
    };

    float ctx[8][4];
#pragma unroll
    for (int i = 0; i < 8; i++)
#pragma unroll
        for (int c = 0; c < 4; c++) ctx[i][c] = 0.f;
    float mrow[2] = {-1e30f, -1e30f};
    float lrow[2] = {0.f, 0.f};

    uint32_t qa[4][4];
    loadQ(); loadKV(0, 0); CP_COMMIT();
    loadKV(1, 1); CP_COMMIT();

    bool qload = false;
    const int m0 = wid * 16;

    for (int kt = 0; kt < 16; kt++) {
        CP_WAIT(1);
        __syncthreads();
        if (!qload) {
#pragma unroll
            for (int kk = 0; kk < 4; kk++)
                ldm_x4(qa[kk], smem_u32(Qs + swz64(m0 + l16, kk*2 + lhi)));
            qload = true;
        }
        const __half* Kb = Ks + (kt & 1) * FKV_ST;
        const __half* Vb = Vs + (kt & 1) * FKV_ST;

        float sacc[8][4];
#pragma unroll
        for (int i = 0; i < 8; i++)
#pragma unroll
            for (int c = 0; c < 4; c++) sacc[i][c] = 0.f;
#pragma unroll
        for (int kk = 0; kk < 4; kk++) {
            uint32_t bf[8][2];
#pragma unroll
            for (int nt = 0; nt < 8; nt++) {
                int row = nt*8 + (l16 & 7);
                ldm_x2(bf[nt], smem_u32(Kb + swz64(row, kk*2 + (l16 >> 3))));
            }
#pragma unroll
            for (int nt = 0; nt < 8; nt++) mma_h(sacc[nt], qa[kk], bf[nt]);
        }
        float nm0 = mrow[0], nm1 = mrow[1];
#pragma unroll
        for (int i = 0; i < 8; i++) {
            sacc[i][0] *= 0.125f; sacc[i][1] *= 0.125f;
            sacc[i][2] *= 0.125f; sacc[i][3] *= 0.125f;
            nm0 = fmaxf(nm0, fmaxf(sacc[i][0], sacc[i][1]));
            nm1 = fmaxf(nm1, fmaxf(sacc[i][2], sacc[i][3]));
        }
        nm0 = fmaxf(nm0, __shfl_xor_sync(0xffffffffu, nm0, 1));
        nm0 = fmaxf(nm0, __shfl_xor_sync(0xffffffffu, nm0, 2));
        nm1 = fmaxf(nm1, __shfl_xor_sync(0xffffffffu, nm1, 1));
        nm1 = fmaxf(nm1, __shfl_xor_sync(0xffffffffu, nm1, 2));
        float f0 = expf(mrow[0] - nm0), f1 = expf(mrow[1] - nm1);
        mrow[0] = nm0; mrow[1] = nm1;
        float rs0 = 0.f, rs1 = 0.f;
        uint32_t pf[8][2];
#pragma unroll
        for (int i = 0; i < 8; i++) {
            float p0 = expf(sacc[i][0] - nm0);
            float p1 = expf(sacc[i][1] - nm0);
            float p2 = expf(sacc[i][2] - nm1);
            float p3 = expf(sacc[i][3] - nm1);
            rs0 += p0 + p1; rs1 += p2 + p3;
            __half2 h01 = __floats2half2_rn(p0, p1);
            __half2 h23 = __floats2half2_rn(p2, p3);
            pf[i][0] = *(uint32_t*)&h01;
            pf[i][1] = *(uint32_t*)&h23;
#pragma unroll
            for (int c = 0; c < 2; c++) ctx[i][c] *= f0;
#pragma unroll
            for (int c = 2; c < 4; c++) ctx[i][c] *= f1;
        }
        rs0 += __shfl_xor_sync(0xffffffffu, rs0, 1);
        rs0 += __shfl_xor_sync(0xffffffffu, rs0, 2);
        rs1 += __shfl_xor_sync(0xffffffffu, rs1, 1);
        rs1 += __shfl_xor_sync(0xffffffffu, rs1, 2);
        lrow[0] = lrow[0] * f0 + rs0;
        lrow[1] = lrow[1] * f1 + rs1;

#pragma unroll
        for (int ks = 0; ks < 4; ks++) {
            uint32_t pa[4];
            pa[0] = pf[2*ks][0];   pa[1] = pf[2*ks][1];
            pa[2] = pf[2*ks+1][0]; pa[3] = pf[2*ks+1][1];
            uint32_t vf[8][2];
#pragma unroll
            for (int nt = 0; nt < 8; nt++)
                ldm_x2t(vf[nt], smem_u32(Vb + swz64(ks*16 + l16, nt)));
#pragma unroll
            for (int nt = 0; nt < 8; nt++) mma_h(ctx[nt], pa, vf[nt]);
        }

        if (kt + 2 < 16) {
            __syncthreads();
            loadKV(kt & 1, kt + 2);
        }
        CP_COMMIT();
    }

    float inv0 = 1.f / lrow[0], inv1 = 1.f / lrow[1];
    int row0 = qt*128 + m0 + g;
    __half* O0 = O + (size_t)b * S_ * D_ + (size_t)row0 * D_ + h*64;
    __half* O1 = O0 + (size_t)8 * D_;
#pragma unroll
    for (int nt = 0; nt < 8; nt++) {
        int col = nt*8 + 2*tg;
        *(__half2*)(O0 + col) = __floats2half2_rn(ctx[nt][0]*inv0, ctx[nt][1]*inv0);
        *(__half2*)(O1 + col) = __floats2half2_rn(ctx[nt][2]*inv1, ctx[nt][3]*inv1);
    }
}

// smem geometry (halves)
#define A_ST   2048
#define BNT_ST 2048
#define BT_ST  2048

// ========== generic fp16 GEMM, BM=BN=128, BK=16, 4-stage cp.async ==========
template<int EPI, bool BTRANS, bool O32, bool O16>
__global__ void __launch_bounds__(256, 2)
gemm_h(const __half* __restrict__ A, const __half* __restrict__ Bm_,
       const float* __restrict__ bias, const float* __restrict__ res,
       float* __restrict__ C32, __half* __restrict__ C16,
       int M, int N, int K, int lda, int ldb, int ldc,
       long long aSB, long long aSH, long long bSB, long long bSH,
       long long cSB, long long cSH) {
    extern __shared__ __align__(16) __half sm[];
    constexpr int BSZ = BTRANS ? BT_ST : BNT_ST;
    __half* Asm = sm;
    __half* Bsm = sm + STAGES*A_ST;

    const int t = threadIdx.x, bm = blockIdx.y, bn = blockIdx.x, z = blockIdx.z;
    A   += (z / H_) * aSB + (z % H_) * aSH;
    Bm_ += (z / H_) * bSB + (z % H_) * bSH;
    long long cOff = (z / H_) * cSB + (z % H_) * cSH;
    const int lane = t & 31, wid = t >> 5;
    const int warpM = wid & 1, warpN = wid >> 1;
    const int g = lane >> 2, tg = lane & 3;

    const int ar = t >> 1, akc = t & 1;
    const int bkr = t >> 4, bcc = t & 15;
    const int aoff = swzA(ar, akc);
    const int boff = swzB(bkr, bcc);

    const __half* Ab0 = A + (size_t)(bm*128) * lda;

    auto issueA = [&](int s, int k0) {
        cp16(smem_u32(Asm + s*A_ST + aoff), Ab0 + (size_t)ar*lda + k0 + akc*8, true);
    };
    auto issueB = [&](int s, int k0) {
        __half* dst = Bsm + s*BSZ;
        if (!BTRANS) {
            bool p = (bn*128 + bcc*8) < N;
            cp16(smem_u32(dst + boff),
                 Bm_ + (size_t)(k0 + bkr)*ldb + bn*128 + bcc*8, p);
        } else {
            bool p = (bn*128 + ar) < N;
            cp16(smem_u32(dst + aoff),
                 Bm_ + (size_t)(bn*128 + ar)*ldb + k0 + akc*8, p);
        }
    };

    float acc[4][4][4];
#pragma unroll
    for (int i = 0; i < 4; i++)
#pragma unroll
        for (int j = 0; j < 4; j++)
#pragma unroll
            for (int c = 0; c < 4; c++) acc[i][j][c] = 0.f;

    const int l16 = lane & 15, lhi = lane >> 4;
    auto compute = [&](int s) {
        const __half* Ab = Asm + s*A_ST;
        const __half* Bb = Bsm + s*BSZ;
        uint32_t af[4][4], bf[4][2];
#pragma unroll
        for (int mt = 0; mt < 4; mt++) {
            int m0 = warpM*64 + mt*16;
            ldm_x4(af[mt], smem_u32(Ab + swzA(m0 + l16, lhi)));
        }
#pragma unroll
        for (int nt = 0; nt < 4; nt++) {
            int n0 = warpN*32 + nt*8;
            if (!BTRANS) ldm_x2t(bf[nt], smem_u32(Bb + swzB(l16, (n0 >> 3))));
            else         ldm_x2 (bf[nt], smem_u32(Bb + swzA(n0 + (l16 & 7), l16 >> 3)));
        }
#pragma unroll
        for (int mt = 0; mt < 4; mt++)
#pragma unroll
            for (int nt = 0; nt < 4; nt++) mma_h(acc[mt][nt], af[mt], bf[nt]);
    };

    const int nT = K >> 4;
#pragma unroll
    for (int s = 0; s < STAGES-1; s++) {
        if (s < nT) { issueA(s, s*16); issueB(s, s*16); }
        CP_COMMIT();
    }
    for (int ti = 0; ti < nT; ti++) {
        CP_WAIT(STAGES-2);
        __syncthreads();
        int nx = ti + STAGES - 1;
        if (nx < nT) { issueA(nx % STAGES, nx*16); issueB(nx % STAGES, nx*16); }
        CP_COMMIT();
        compute(ti % STAGES);
    }
#pragma unroll
    for (int mt = 0; mt < 4; mt++)
#pragma unroll
        for (int nt = 0; nt < 4; nt++) {
            int col = bn*128 + warpN*32 + nt*8 + 2*tg;
            if (col >= N) continue;
#pragma unroll
            for (int h = 0; h < 2; h++) {
                int row = bm*128 + warpM*64 + mt*16 + g + h*8;
                float v0 = acc[mt][nt][2*h], v1 = acc[mt][nt][2*h+1];
                if (EPI == 1 || EPI == 2 || EPI == 3) { v0 += bias[col]; v1 += bias[col+1]; }
                if (EPI == 2) { v0 = gelu_f(v0); v1 = gelu_f(v1); }
                if (EPI == 3) { size_t o = (size_t)row*ldc + col; v0 += res[o]; v1 += res[o+1]; }
                size_t o = cOff + (size_t)row*ldc + col;
                if (O32) *(float2*)(C32 + o) = make_float2(v0, v1);
                if (O16) *(__half2*)(C16 + o) = __floats2half2_rn(v0, v1);
            }
        }
}

// ========== split-K GEMM, dual-weight: z%nsplit = K-slice, z/nsplit selects W ==========
// M=BS_, N=D_ fixed; B nontrans row stride D_. Partials P[z].
__global__ void __launch_bounds__(256, 2)
gemm_splitk(const __half* __restrict__ A, const __half* __restrict__ W0,
            const __half* __restrict__ W1, float* __restrict__ P,
            int Ks, int lda, int nsplit) {
    extern __shared__ __align__(16) __half sm[];
    __half* Asm = sm;
    __half* Bsm = sm + STAGES*A_ST;

    const int t = threadIdx.x, bm = blockIdx.y, bn = blockIdx.x, z = blockIdx.z;
    const int kbase = (z % nsplit) * Ks;
    const __half* W = (z < nsplit) ? W0 : W1;
    const int lane = t & 31, wid = t >> 5;
    const int warpM = wid & 1, warpN = wid >> 1;
    const int g = lane >> 2, tg = lane & 3;

    const int ar = t >> 1, akc = t & 1;
    const int bkr = t >> 4, bcc = t & 15;
    const int aoff = swzA(ar, akc);
    const int boff = swzB(bkr, bcc);

    const __half* Ab0 = A + (size_t)(bm*128) * lda + kbase;
    const __half* Bb0 = W + (size_t)kbase * D_;

    auto issueA = [&](int s, int k0) {
        cp16(smem_u32(Asm + s*A_ST + aoff), Ab0 + (size_t)ar*lda + k0 + akc*8, true);
    };
    auto issueB = [&](int s, int k0) {
        cp16(smem_u32(Bsm + s*BNT_ST + boff),
             Bb0 + (size_t)(k0 + bkr)*D_ + bn*128 + bcc*8, true);
    };

    float acc[4][4][4];
#pragma unroll
    for (int i = 0; i < 4; i++)
#pragma unroll
        for (int j = 0; j < 4; j++)
#pragma unroll
            for (int c = 0; c < 4; c++) acc[i][j][c] = 0.f;

    const int l16 = lane & 15, lhi = lane >> 4;
    auto compute = [&](int s) {
        const __half* Ab = Asm + s*A_ST;
        const __half* Bb = Bsm + s*BNT_ST;
        uint32_t af[4][4], bf[4][2];
#pragma unroll
        for (int mt = 0; mt < 4; mt++)
            ldm_x4(af[mt], smem_u32(Ab + swzA(warpM*64 + mt*16 + l16, lhi)));
#pragma unroll
        for (int nt = 0; nt < 4; nt++)
            ldm_x2t(bf[nt], smem_u32(Bb + swzB(l16, warpN*4 + nt)));
#pragma unroll
        for (int mt = 0; mt < 4; mt++)
#pragma unroll
            for (int nt = 0; nt < 4; nt++) mma_h(acc[mt][nt], af[mt], bf[nt]);
    };

    const int nT = Ks >> 4;
#pragma unroll
    for (int s = 0; s < STAGES-1; s++) {
        if (s < nT) { issueA(s, s*16); issueB(s, s*16); }
        CP_COMMIT();
    }
    for (int ti = 0; ti < nT; ti++) {
        CP_WAIT(STAGES-2);
        __syncthreads();
        int nx = ti + STAGES - 1;
        if (nx < nT) { issueA(nx % STAGES, nx*16); issueB(nx % STAGES, nx*16); }
        CP_COMMIT();
        compute(ti % STAGES);
    }
    float* Pz = P + (size_t)z * BS_ * D_;
#pragma unroll
    for (int mt = 0; mt < 4; mt++)
#pragma unroll
        for (int nt = 0; nt < 4; nt++) {
            int col = bn*128 + warpN*32 + nt*8 + 2*tg;
#pragma unroll
            for (int h = 0; h < 2; h++) {
                int row = bm*128 + warpM*64 + mt*16 + g + h*8;
                *(float2*)(Pz + (size_t)row*D_ + col) =
                    make_float2(acc[mt][nt][2*h], acc[mt][nt][2*h+1]);
            }
        }
}

// ---- combine 4 split-K partials + bias (+ residual) -> fp32/fp16 ----
template<bool O32, bool O16, bool RES>
__global__ void combine4(const float* __restrict__ P, const float* __restrict__ bias,
                         const float* __restrict__ res, float* __restrict__ o32,
                         __half* __restrict__ o16) {
    size_t i = ((size_t)blockIdx.x * 256 + threadIdx.x) * 2;
    const size_t MN = (size_t)BS_ * D_;
    float2 v0 = *(const float2*)(P + i);
    float2 v1 = *(const float2*)(P + MN + i);
    float2 v2 = *(const float2*)(P + 2*MN + i);
    float2 v3 = *(const float2*)(P + 3*MN + i);
    int col = (int)(i % D_);
    float a = v0.x + v1.x + v2.x + v3.x + bias[col];
    float b = v0.y + v1.y + v2.y + v3.y + bias[col + 1];
    if (RES) { a += res[i]; b += res[i + 1]; }
    if (O32) *(float2*)(o32 + i) = make_float2(a, b);
    if (O16) *(__half2*)(o16 + i) = __floats2half2_rn(a, b);
}

// ---- combine A/Bm: y=0 -> A = P0+P1+bias; y=1 -> Bm = P2+P3 ----
__global__ void combineAB(const float* __restrict__ P, const float* __restrict__ b1,
                          float* __restrict__ A, float* __restrict__ Bm) {
    size_t i = ((size_t)blockIdx.x * 256 + threadIdx.x) * 2;
    const size_t MN = (size_t)BS_ * D_;
    if (blockIdx.y == 0) {
        float2 v0 = *(const float2*)(P + i);
        float2 v1 = *(const float2*)(P + MN + i);
        int col = (int)(i % D_);
        *(float2*)(A + i) = make_float2(v0.x + v1.x + b1[col], v0.y + v1.y + b1[col + 1]);
    } else {
        float2 v0 = *(const float2*)(P + 2*MN + i);
        float2 v1 = *(const float2*)(P + 3*MN + i);
        *(float2*)(Bm + i) = make_float2(v0.x + v1.x, v0.y + v1.y);
    }
}

// ========== multi-output GEMM (QKV fused) ==========
struct MultiP {
    const __half* W[3];
    const float*  bias[3];
    float*        C32[3];
    __half*       C16[3];
};
__global__ void __launch_bounds__(256, 2)
gemm_multi(const __half* __restrict__ A, MultiP p, int nbnper, int K, int lda) {
    extern __shared__ __align__(16) __half sm[];
    __half* Asm = sm;
    __half* Bsm = sm + STAGES*A_ST;

    const int t = threadIdx.x, bm = blockIdx.y, bnG = blockIdx.x;
    const int sel = bnG / nbnper, bn = bnG % nbnper;
    const __half* W = p.W[sel];
    const float* bias = p.bias[sel];
    float* C32 = p.C32[sel];
    __half* C16 = p.C16[sel];

    const int lane = t & 31, wid = t >> 5;
    const int warpM = wid & 1, warpN = wid >> 1;
    const int g = lane >> 2, tg = lane & 3;
    const int ar = t >> 1, akc = t & 1;
    const int bkr = t >> 4, bcc = t & 15;
    const int aoff = swzA(ar, akc);
    const int boff = swzB(bkr, bcc);
    const __half* Ab0 = A + (size_t)(bm*128) * lda;

    auto issueA = [&](int s, int k0) {
        cp16(smem_u32(Asm + s*A_ST + aoff), Ab0 + (size_t)ar*lda + k0 + akc*8, true);
    };
    auto issueB = [&](int s, int k0) {
        cp16(smem_u32(Bsm + s*BNT_ST + boff),
             W + (size_t)(k0 + bkr)*D_ + bn*128 + bcc*8, true);
    };

    float acc[4][4][4];
#pragma unroll
    for (int i = 0; i < 4; i++)
#pragma unroll
        for (int j = 0; j < 4; j++)
#pragma unroll
            for (int c = 0; c < 4; c++) acc[i][j][c] = 0.f;

    const int l16 = lane & 15, lhi = lane >> 4;
    auto compute = [&](int s) {
        const __half* Ab = Asm + s*A_ST;
        const __half* Bb = Bsm + s*BNT_ST;
        uint32_t af[4][4], bf[4][2];
#pragma unroll
        for (int mt = 0; mt < 4; mt++)
            ldm_x4(af[mt], smem_u32(Ab + swzA(warpM*64 + mt*16 + l16, lhi)));
#pragma unroll
        for (int nt = 0; nt < 4; nt++)
            ldm_x2t(bf[nt], smem_u32(Bb + swzB(l16, warpN*4 + nt)));
#pragma unroll
        for (int mt = 0; mt < 4; mt++)
#pragma unroll
            for (int nt = 0; nt < 4; nt++) mma_h(acc[mt][nt], af[mt], bf[nt]);
    };

    const int nT = K >> 4;
#pragma unroll
    for (int s = 0; s < STAGES-1; s++) {
        if (s < nT) { issueA(s, s*16); issueB(s, s*16); }
        CP_COMMIT();
    }
    for (int ti = 0; ti < nT; ti++) {
        CP_WAIT(STAGES-2);
        __syncthreads();
        int nx = ti + STAGES - 1;
        if (nx < nT) { issueA(nx % STAGES, nx*16); issueB(nx % STAGES, nx*16); }
        CP_COMMIT();
        compute(ti % STAGES);
    }
#pragma unroll
    for (int mt = 0; mt < 4; mt++)
#pragma unroll
        for (int nt = 0; nt < 4; nt++) {
            int col = bn*128 + warpN*32 + nt*8 + 2*tg;
#pragma unroll
            for (int h = 0; h < 2; h++) {
                int row = bm*128 + warpM*64 + mt*16 + g + h*8;
                float v0 = acc[mt][nt][2*h], v1 = acc[mt][nt][2*h+1];
                if (bias) { v0 += bias[col]; v1 += bias[col+1]; }
                size_t o = (size_t)row*D_ + col;
                if (C32) *(float2*)(C32 + o) = make_float2(v0, v1);
                if (C16) *(__half2*)(C16 + o) = __floats2half2_rn(v0, v1);
            }
        }
}

// ---------------- row LayerNorm (width 768) -> fp16 out ----------------
__launch_bounds__(256)
__global__ void ln_kernel(const float* __restrict__ x, const float* __restrict__ g,
                          const float* __restrict__ b, __half* __restrict__ out) {
    const int r = blockIdx.x, t = threadIdx.x;
    __shared__ float rs[8], rq[8], stat[2];
    const float* row = x + (size_t)r * D_;
    float v0 = row[t], v1 = row[t + 256], v2 = row[t + 512];
    float s = v0 + v1 + v2;
    float q = v0*v0 + v1*v1 + v2*v2;
#pragma unroll
    for (int o = 16; o > 0; o >>= 1) {
        s += __shfl_xor_sync(0xffffffffu, s, o);
        q += __shfl_xor_sync(0xffffffffu, q, o);
    }
    if ((t & 31) == 0) { rs[t >> 5] = s; rq[t >> 5] = q; }
    __syncthreads();
    if (t == 0) {
        float S = 0.f, Q = 0.f;
        for (int w = 0; w < 8; w++) { S += rs[w]; Q += rq[w]; }
        float mean = S * (1.f/768.f);
        float var  = Q * (1.f/768.f) - mean*mean;
        stat[0] = mean; stat[1] = rsqrtf(var + 1e-5f);
    }
    __syncthreads();
    float mean = stat[0], rstd = stat[1];
    __half* o = out + (size_t)r * D_;
    o[t]       = __float2half((v0 - mean) * rstd * g[t]       + b[t]);
    o[t + 256] = __float2half((v1 - mean) * rstd * g[t + 256] + b[t + 256]);
    o[t + 512] = __float2half((v2 - mean) * rstd * g[t + 512] + b[t + 512]);
}

// ---- relreduce: warp-per-j-row LN + mean over j + residual + fused LN2 ----
__launch_bounds__(256)
__global__ void relreduce(const __half* __restrict__ Hp, const float* __restrict__ g,
                          const float* __restrict__ bln, const float* __restrict__ x1,
                          float* __restrict__ x2,
                          const float* __restrict__ ln2g, const float* __restrict__ ln2b,
                          __half* __restrict__ hout) {
    const int bci = blockIdx.x, t = threadIdx.x;
    const int w = t >> 5, lane = t & 31;
    __shared__ float smacc[8][768];
    __shared__ float rs[8], rq[8], stat[2];

    float acc[24];
#pragma unroll
    for (int e = 0; e < 24; e++) acc[e] = 0.f;

    const __half* base = Hp + (size_t)bci * 64 * D_;
    for (int jj = 0; jj < 8; jj++) {
        const __half2* row = (const __half2*)(base + (size_t)(w + jj*8) * D_);
        float v[24]; float s = 0.f, q = 0.f;
#pragma unroll
        for (int e = 0; e < 12; e++) {
            float2 f = __half22float2(row[lane + 32*e]);
            v[2*e] = f.x; v[2*e+1] = f.y;
            s += f.x + f.y; q += f.x*f.x + f.y*f.y;
        }
#pragma unroll
        for (int o = 16; o > 0; o >>= 1) {
            s += __shfl_xor_sync(0xffffffffu, s, o);
            q += __shfl_xor_sync(0xffffffffu, q, o);
        }
        float mean = s * (1.f/768.f);
        float rstd = rsqrtf(q * (1.f/768.f) - mean*mean + 1e-5f);
#pragma unroll
        for (int e = 0; e < 24; e++) acc[e] += (v[e] - mean) * rstd;
    }
#pragma unroll
    for (int e = 0; e < 12; e++) {
        smacc[w][2*(lane + 32*e)]     = acc[2*e];
        smacc[w][2*(lane + 32*e) + 1] = acc[2*e+1];
    }
    __syncthreads();

    float o0 = 0.f, o1 = 0.f, o2 = 0.f;
#pragma unroll
    for (int w8 = 0; w8 < 8; w8++) {
        o0 += smacc[w8][t];
        o1 += smacc[w8][t + 256];
        o2 += smacc[w8][t + 512];
    }
    size_t off = (size_t)bci * D_;
    o0 = x1[off + t]       + o0 * (1.f/64.f) * g[t]       + bln[t];
    o1 = x1[off + t + 256] + o1 * (1.f/64.f) * g[t + 256] + bln[t + 256];
    o2 = x1[off + t + 512] + o2 * (1.f/64.f) * g[t + 512] + bln[t + 512];
    x2[off + t] = o0; x2[off + t + 256] = o1; x2[off + t + 512] = o2;

    float s = o0 + o1 + o2, q = o0*o0 + o1*o1 + o2*o2;
#pragma unroll
    for (int o = 16; o > 0; o >>= 1) {
        s += __shfl_xor_sync(0xffffffffu, s, o);
        q += __shfl_xor_sync(0xffffffffu, q, o);
    }
    if (lane == 0) { rs[w] = s; rq[w] = q; }
    __syncthreads();
    if (t == 0) {
        float S = 0.f, Q = 0.f;
        for (int w8 = 0; w8 < 8; w8++) { S += rs[w8]; Q += rq[w8]; }
        float mean = S * (1.f/768.f);
        float var  = Q * (1.f/768.f) - mean*mean;
        stat[0] = mean; stat[1] = rsqrtf(var + 1e-5f);
    }
    __syncthreads();
    float mean = stat[0], rstd = stat[1];
    hout[off + t]       = __float2half((o0 - mean) * rstd * ln2g[t]       + ln2b[t]);
    hout[off + t + 256] = __float2half((o1 - mean) * rstd * ln2g[t + 256] + ln2b[t + 256]);
    hout[off + t + 512] = __float2half((o2 - mean) * rstd * ln2g[t + 512] + ln2b[t + 512]);
}

// ---------------- host orchestration ----------------
static float  *P_x1, *P_A, *P_Bm, *P_x2;
static __half *P_Hp, *P_G;
static __half *P_hh, *P_qh, *P_kh, *P_vh, *P_ctxh, *P_x1h, *P_fh;
static __half *P_Wqh, *P_Wkh, *P_Wvh, *P_Woh, *P_W1h, *P_W2h, *P_E1h, *P_E2h;
static bool g_init = false;

#define SM_NT  ((STAGES*A_ST + STAGES*BNT_ST)*2)   // 32768
#define SM_FL  ((FQ_ST + 4*FKV_ST)*2)              // 49152

extern "C" void kernel_launch(void* const* d_in, const int* in_sizes, int n_in,
                              void* d_out, int out_size) {
    if (!g_init) {
        cudaGetSymbolAddress((void**)&P_x1,  g_x1);
        cudaGetSymbolAddress((void**)&P_A,   g_A);
        cudaGetSymbolAddress((void**)&P_Bm,  g_Bm);
        cudaGetSymbolAddress((void**)&P_x2,  g_x2);
        cudaGetSymbolAddress((void**)&P_Hp,  g_Hp);
        cudaGetSymbolAddress((void**)&P_G,   g_G);
        cudaGetSymbolAddress((void**)&P_hh,  g_hh);
        cudaGetSymbolAddress((void**)&P_qh,  g_qh);
        cudaGetSymbolAddress((void**)&P_kh,  g_kh);
        cudaGetSymbolAddress((void**)&P_vh,  g_vh);
        cudaGetSymbolAddress((void**)&P_ctxh,g_ctxh);
        cudaGetSymbolAddress((void**)&P_x1h, g_x1h);
        cudaGetSymbolAddress((void**)&P_fh,  g_fh);
        cudaGetSymbolAddress((void**)&P_Wqh, g_Wqh);
        cudaGetSymbolAddress((void**)&P_Wkh, g_Wkh);
        cudaGetSymbolAddress((void**)&P_Wvh, g_Wvh);
        cudaGetSymbolAddress((void**)&P_Woh, g_Woh);
        cudaGetSymbolAddress((void**)&P_W1h, g_W1h);
        cudaGetSymbolAddress((void**)&P_W2h, g_W2h);
        cudaGetSymbolAddress((void**)&P_E1h, g_E1h);
        cudaGetSymbolAddress((void**)&P_E2h, g_E2h);
        cudaFuncSetAttribute(gemm_h<2,false,false,true>, cudaFuncAttributeMaxDynamicSharedMemorySize, SM_NT);
        cudaFuncSetAttribute(gemm_h<1,false,false,true>, cudaFuncAttributeMaxDynamicSharedMemorySize, SM_NT);
        cudaFuncSetAttribute(gemm_multi,  cudaFuncAttributeMaxDynamicSharedMemorySize, SM_NT);
        cudaFuncSetAttribute(gemm_splitk, cudaFuncAttributeMaxDynamicSharedMemorySize, SM_NT);
        cudaFuncSetAttribute(flash_attn,  cudaFuncAttributeMaxDynamicSharedMemorySize, SM_FL);
        g_init = true;
    }
    const float* x      = (const float*)d_in[0];
    const float* Wq     = (const float*)d_in[1];
    const float* bq     = (const float*)d_in[2];
    const float* Wk     = (const float*)d_in[3];
    const float* bk     = (const float*)d_in[4];
    const float* Wv     = (const float*)d_in[5];
    const float* bv     = (const float*)d_in[6];
    const float* Wo     = (const float*)d_in[7];
    const float* bo     = (const float*)d_in[8];
    const float* ln1_g  = (const float*)d_in[9];
    const float* ln1_b  = (const float*)d_in[10];
    const float* rel_W1 = (const float*)d_in[11];
    const float* rel_b1 = (const float*)d_in[12];
    const float* rel_W2 = (const float*)d_in[13];
    const float* rel_b2 = (const float*)d_in[14];
    const float* rel_ln_g = (const float*)d_in[15];
    const float* rel_ln_b = (const float*)d_in[16];
    const float* ln2_g  = (const float*)d_in[17];
    const float* ln2_b  = (const float*)d_in[18];
    const float* enc_W1 = (const float*)d_in[19];
    const float* enc_b1 = (const float*)d_in[20];
    const float* enc_W2 = (const float*)d_in[21];
    const float* enc_b2 = (const float*)d_in[22];
    float* out = (float*)d_out;

    const int DD = D_ * D_;
    float* PK = (float*)P_Hp;          // split-K scratch inside dead Hp buffer
    const int CGRID = BS_*D_/512;

    // 0) fused weight conversions
    {
        ConvP p;
        p.src[0]=Wq;    p.dst[0]=P_Wqh;
        p.src[1]=Wk;    p.dst[1]=P_Wkh;
        p.src[2]=Wv;    p.dst[2]=P_Wvh;
        p.src[3]=Wo;    p.dst[3]=P_Woh;
        p.src[4]=rel_W1;p.dst[4]=P_W1h;
        p.src[5]=rel_W2;p.dst[5]=P_W2h;
        p.src[6]=enc_W1;p.dst[6]=P_E1h;
        p.src[7]=enc_W2;p.dst[7]=P_E2h;
        int sz[8] = {DD, DD, DD, DD, 2*DD, DD, D_*DFF_, D_*DFF_};
        p.off[0] = 0;
        for (int k = 0; k < 8; k++) p.off[k+1] = p.off[k] + sz[k];
        int total = p.off[8];
        conv_all<<<(total/4 + 255)/256, 256>>>(p);
    }

    // 1) h = LN1(x) -> fp16
    ln_kernel<<<BS_, 256>>>(x, ln1_g, ln1_b, P_hh);
    // 2) fused QKV
    {
        MultiP p;
        p.W[0]=P_Wqh; p.W[1]=P_Wkh; p.W[2]=P_Wvh;
        p.bias[0]=bq; p.bias[1]=bk; p.bias[2]=bv;
        p.C32[0]=p.C32[1]=p.C32[2]=nullptr;
        p.C16[0]=P_qh; p.C16[1]=P_kh; p.C16[2]=P_vh;
        gemm_multi<<<dim3(18,16), 256, SM_NT>>>(P_hh, p, 6, D_, D_);
    }
    // 3) fused flash attention
    flash_attn<<<dim3(8, B_*H_), 256, SM_FL>>>(P_qh, P_kh, P_vh, P_ctxh);
    // 4) x1 = x + ctx@Wo + bo  (split-K=4)
    gemm_splitk<<<dim3(6,16,4), 256, SM_NT>>>(P_ctxh, P_Woh, nullptr, PK, 192, D_, 4);
    combine4<true,true,true><<<CGRID, 256>>>(PK, bo, x, P_x1, P_x1h);
    // 5) A / Bm via dual-weight split-K=2 (full chip)
    gemm_splitk<<<dim3(6,16,4), 256, SM_NT>>>(P_x1h, P_W1h, P_W1h + DD, PK, 384, D_, 2);
    combineAB<<<dim3(CGRID, 2), 256>>>(PK, rel_b1, P_A, P_Bm);
    // 6) relation
    gelu_mat<<<dim3(2048, 2), 192>>>(P_A, P_Bm, P_G);
    gemm_h<1,false,false,true><<<dim3(6,1024), 256, SM_NT>>>(
        P_G, P_W2h, rel_b2, nullptr, nullptr, P_Hp,
        MREL, D_, D_, D_, D_, D_, 0,0,0,0,0,0);
    relreduce<<<BS_, 256>>>(P_Hp, rel_ln_g, rel_ln_b, P_x1, P_x2, ln2_g, ln2_b, P_hh);
    // 7) FFN: up-proj+gelu, then down-proj via split-K=4
    gemm_h<2,false,false,true><<<dim3(24,16), 256, SM_NT>>>(
        P_hh, P_E1h, enc_b1, nullptr, nullptr, P_fh,
        BS_, DFF_, D_, D_, DFF_, DFF_, 0,0,0,0,0,0);
    gemm_splitk<<<dim3(6,16,4), 256, SM_NT>>>(P_fh, P_E2h, nullptr, PK, 768, DFF_, 4);
    combine4<true,false,true><<<CGRID, 256>>>(PK, enc_b2, P_x2, out, nullptr);
}

// round 17
// speedup vs baseline: 1.0156x; 1.0156x over previous
#include <cuda_runtime.h>
#include <cuda_fp16.h>
#include <math.h>
#include <stdint.h>

#define B_   2
#define S_   1024
#define D_   768
#define H_   12
#define DFF_ 3072
#define BS_  2048
#define MREL 131072
#define STAGES 4

// ---------------- scratch ----------------
__device__ float  g_x1 [BS_*D_];
__device__ float  g_A  [BS_*D_];
__device__ float  g_Bm [BS_*D_];
__device__ float  g_x2 [BS_*D_];
__device__ __half g_Hp [(size_t)MREL*D_];   // relation out fp16; also fp32 split-K scratch
__device__ __half g_G  [(size_t)MREL*D_];
__device__ __half g_hh [BS_*D_];
__device__ __half g_qh [BS_*D_];
__device__ __half g_kh [BS_*D_];
__device__ __half g_vh [BS_*D_];
__device__ __half g_ctxh[BS_*D_];
__device__ __half g_x1h[BS_*D_];
__device__ __half g_fh [BS_*DFF_];
// fp16 weights
__device__ __half g_Wqh[D_*D_], g_Wkh[D_*D_], g_Wvh[D_*D_], g_Woh[D_*D_];
__device__ __half g_W1h[2*D_*D_], g_W2h[D_*D_];
__device__ __half g_E1h[D_*DFF_], g_E2h[DFF_*D_];

__device__ __forceinline__ float gelu_f(float x) {
    return 0.5f * x * (1.0f + erff(x * 0.70710678118654752f));
}
__device__ __forceinline__ uint32_t smem_u32(const void* p) {
    return (uint32_t)__cvta_generic_to_shared(p);
}
__device__ __forceinline__ void cp16(uint32_t dst, const void* src, bool pred) {
    int sz = pred ? 16 : 0;
    asm volatile("cp.async.cg.shared.global [%0], [%1], 16, %2;\n"
                 :: "r"(dst), "l"(src), "r"(sz));
}
#define CP_COMMIT() asm volatile("cp.async.commit_group;\n")
#define CP_WAIT(n)  asm volatile("cp.async.wait_group %0;\n" :: "n"(n))

__device__ __forceinline__ void ldm_x4(uint32_t* r, uint32_t a) {
    asm volatile("ldmatrix.sync.aligned.m8n8.x4.shared.b16 {%0,%1,%2,%3},[%4];"
                 : "=r"(r[0]), "=r"(r[1]), "=r"(r[2]), "=r"(r[3]) : "r"(a));
}
__device__ __forceinline__ void ldm_x2t(uint32_t* r, uint32_t a) {
    asm volatile("ldmatrix.sync.aligned.m8n8.x2.trans.shared.b16 {%0,%1},[%2];"
                 : "=r"(r[0]), "=r"(r[1]) : "r"(a));
}
__device__ __forceinline__ void ldm_x2(uint32_t* r, uint32_t a) {
    asm volatile("ldmatrix.sync.aligned.m8n8.x2.shared.b16 {%0,%1},[%2];"
                 : "=r"(r[0]), "=r"(r[1]) : "r"(a));
}
__device__ __forceinline__ void mma_h(float* c, const uint32_t* a, const uint32_t* b) {
    asm volatile(
        "mma.sync.aligned.m16n8k16.row.col.f32.f16.f16.f32 "
        "{%0,%1,%2,%3},{%4,%5,%6,%7},{%8,%9},{%0,%1,%2,%3};\n"
        : "+f"(c[0]), "+f"(c[1]), "+f"(c[2]), "+f"(c[3])
        : "r"(a[0]), "r"(a[1]), "r"(a[2]), "r"(a[3]), "r"(b[0]), "r"(b[1]));
}

// -------- conflict-free swizzled smem offsets (in halves) --------
__device__ __forceinline__ int swzA(int row, int kc) {
    int idx = 2*row + kc;
    int L = idx >> 3;
    return (L << 6) + ((((idx & 7) ^ (L & 7))) << 3);
}
__device__ __forceinline__ int swzB(int k, int cc) {
    return ((2*k + (cc >> 3)) << 6) + (((cc & 7) ^ (k & 7)) << 3);
}
__device__ __forceinline__ int swz64(int row, int c) {
    return (row << 6) + (((c ^ (row & 7))) << 3);
}

// ---------------- fused fp32 -> fp16 conversion over 8 segments ----------------
struct ConvP {
    const float* src[8];
    __half* dst[8];
    int off[9];
};
__global__ void conv_all(ConvP p) {
    int e = (blockIdx.x * 256 + threadIdx.x) * 4;
    if (e >= p.off[8]) return;
    int s = 0;
#pragma unroll
    for (int k = 0; k < 7; k++) s += (e >= p.off[k+1]);
    int le = e - p.off[s];
    float4 v = *(const float4*)(p.src[s] + le);
    __half2 a = __floats2half2_rn(v.x, v.y);
    __half2 b = __floats2half2_rn(v.z, v.w);
    *(uint2*)(p.dst[s] + le) = make_uint2(*(uint32_t*)&a, *(uint32_t*)&b);
}

// ---------------- G = gelu(A_i + B_j) materialization (fp16) ----------------
__global__ void __launch_bounds__(192)
gelu_mat(const float* __restrict__ A, const float* __restrict__ Bm,
         __half* __restrict__ G) {
    const int bx = blockIdx.x, jh = blockIdx.y, t = threadIdx.x;
    const int cb = (bx >> 6) << 6;
    const int i  = bx & 63;
    float4 a = *(const float4*)(A + (size_t)(cb + i) * D_ + t*4);
    const float* Bbase = Bm + (size_t)cb * D_ + t*4;
    __half* Gb = G + (size_t)bx * 64 * D_ + t*4;
#pragma unroll 4
    for (int j = jh*32; j < jh*32 + 32; j++) {
        float4 b = *(const float4*)(Bbase + (size_t)j * D_);
        __half2 h0 = __floats2half2_rn(gelu_f(a.x+b.x), gelu_f(a.y+b.y));
        __half2 h1 = __floats2half2_rn(gelu_f(a.z+b.z), gelu_f(a.w+b.w));
        *(uint2*)(Gb + (size_t)j * D_) = make_uint2(*(uint32_t*)&h0, *(uint32_t*)&h1);
    }
}

// ================== flash attention (register-resident P) ==========
#define FQ_ST 8192
#define FKV_ST 4096
__global__ void __launch_bounds__(256, 2)
flash_attn(const __half* __restrict__ Q, const __half* __restrict__ K,
           const __half* __restrict__ V, __half* __restrict__ O) {
    extern __shared__ __align__(16) __half sm[];
    __half* Qs = sm;
    __half* Ks = sm + FQ_ST;
    __half* Vs = sm + FQ_ST + 2*FKV_ST;

    const int t = threadIdx.x, qt = blockIdx.x, bh = blockIdx.y;
    const int b = bh / H_, h = bh % H_;
    const int lane = t & 31, wid = t >> 5;
    const int g = lane >> 2, tg = lane & 3;
    const int l16 = lane & 15, lhi = lane >> 4;

    const __half* Qg = Q + (size_t)b * S_ * D_ + h * 64;
    const __half* Kg = K + (size_t)b * S_ * D_ + h * 64;
    const __half* Vg = V + (size_t)b * S_ * D_ + h * 64;

    auto loadQ = [&]() {
#pragma unroll
        for (int i = 0; i < 4; i++) {
            int cid = t + i*256;
            int r = cid >> 3, c = cid & 7;
            cp16(smem_u32(Qs + swz64(r, c)),
                 Qg + (size_t)(qt*128 + r) * D_ + c*8, true);
        }
    };
    auto loadKV = [&](int st, int kt) {
#pragma unroll
        for (int i = 0; i < 2; i++) {
            int cid = t + i*256;
            int r = cid >> 3, c = cid & 7;
            cp16(smem_u32(Ks + st*FKV_ST + swz64(r, c)),
                 Kg + (size_t)(kt*64 + r) * D_ + c*8, true);
        }
#pragma unroll
        for (int i = 0; i < 2; i++) {
            int cid = t + i*256;
            int r = cid >> 3, c = cid & 7;
            cp16(smem_u32(Vs + st*FKV_ST + swz64(r, c)),
                 Vg + (size_t)(kt*64 + r) * D_ + c*8, true);
        }
    };

    float ctx[8][4];
#pragma unroll
    for (int i = 0; i < 8; i++)
#pragma unroll
        for (int c = 0; c < 4; c++) ctx[i][c] = 0.f;
    float mrow[2] = {-1e30f, -1e30f};
    float lrow[2] = {0.f, 0.f};

    uint32_t qa[4][4];
    loadQ(); loadKV(0, 0); CP_COMMIT();
    loadKV(1, 1); CP_COMMIT();

    bool qload = false;
    const int m0 = wid * 16;

    for (int kt = 0; kt < 16; kt++) {
        CP_WAIT(1);
        __syncthreads();
        if (!qload) {
#pragma unroll
            for (int kk = 0; kk < 4; kk++)
                ldm_x4(qa[kk], smem_u32(Qs + swz64(m0 + l16, kk*2 + lhi)));
            qload = true;
        }
        const __half* Kb = Ks + (kt & 1) * FKV_ST;
        const __half* Vb = Vs + (kt & 1) * FKV_ST;

        float sacc[8][4];
#pragma unroll
        for (int i = 0; i < 8; i++)
#pragma unroll
            for (int c = 0; c < 4; c++) sacc[i][c] = 0.f;
#pragma unroll
        for (int kk = 0; kk < 4; kk++) {
            uint32_t bf[8][2];
#pragma unroll
            for (int nt = 0; nt < 8; nt++) {
                int row = nt*8 + (l16 & 7);
                ldm_x2(bf[nt], smem_u32(Kb + swz64(row, kk*2 + (l16 >> 3))));
            }
#pragma unroll
            for (int nt = 0; nt < 8; nt++) mma_h(sacc[nt], qa[kk], bf[nt]);
        }
        float nm0 = mrow[0], nm1 = mrow[1];
#pragma unroll
        for (int i = 0; i < 8; i++) {
            sacc[i][0] *= 0.125f; sacc[i][1] *= 0.125f;
            sacc[i][2] *= 0.125f; sacc[i][3] *= 0.125f;
            nm0 = fmaxf(nm0, fmaxf(sacc[i][0], sacc[i][1]));
            nm1 = fmaxf(nm1, fmaxf(sacc[i][2], sacc[i][3]));
        }
        nm0 = fmaxf(nm0, __shfl_xor_sync(0xffffffffu, nm0, 1));
        nm0 = fmaxf(nm0, __shfl_xor_sync(0xffffffffu, nm0, 2));
        nm1 = fmaxf(nm1, __shfl_xor_sync(0xffffffffu, nm1, 1));
        nm1 = fmaxf(nm1, __shfl_xor_sync(0xffffffffu, nm1, 2));
        float f0 = __expf(mrow[0] - nm0), f1 = __expf(mrow[1] - nm1);
        mrow[0] = nm0; mrow[1] = nm1;
        float rs0 = 0.f, rs1 = 0.f;
        uint32_t pf[8][2];
#pragma unroll
        for (int i = 0; i < 8; i++) {
            float p0 = __expf(sacc[i][0] - nm0);
            float p1 = __expf(sacc[i][1] - nm0);
            float p2 = __expf(sacc[i][2] - nm1);
            float p3 = __expf(sacc[i][3] - nm1);
            rs0 += p0 + p1; rs1 += p2 + p3;
            __half2 h01 = __floats2half2_rn(p0, p1);
            __half2 h23 = __floats2half2_rn(p2, p3);
            pf[i][0] = *(uint32_t*)&h01;
            pf[i][1] = *(uint32_t*)&h23;
#pragma unroll
            for (int c = 0; c < 2; c++) ctx[i][c] *= f0;
#pragma unroll
            for (int c = 2; c < 4; c++) ctx[i][c] *= f1;
        }
        rs0 += __shfl_xor_sync(0xffffffffu, rs0, 1);
        rs0 += __shfl_xor_sync(0xffffffffu, rs0, 2);
        rs1 += __shfl_xor_sync(0xffffffffu, rs1, 1);
        rs1 += __shfl_xor_sync(0xffffffffu, rs1, 2);
        lrow[0] = lrow[0] * f0 + rs0;
        lrow[1] = lrow[1] * f1 + rs1;

#pragma unroll
        for (int ks = 0; ks < 4; ks++) {
            uint32_t pa[4];
            pa[0] = pf[2*ks][0];   pa[1] = pf[2*ks][1];
            pa[2] = pf[2*ks+1][0]; pa[3] = pf[2*ks+1][1];
            uint32_t vf[8][2];
#pragma unroll
            for (int nt = 0; nt < 8; nt++)
                ldm_x2t(vf[nt], smem_u32(Vb + swz64(ks*16 + l16, nt)));
#pragma unroll
            for (int nt = 0; nt < 8; nt++) mma_h(ctx[nt], pa, vf[nt]);
        }

        if (kt + 2 < 16) {
            __syncthreads();
            loadKV(kt & 1, kt + 2);
        }
        CP_COMMIT();
    }

    float inv0 = 1.f / lrow[0], inv1 = 1.f / lrow[1];
    int row0 = qt*128 + m0 + g;
    __half* O0 = O + (size_t)b * S_ * D_ + (size_t)row0 * D_ + h*64;
    __half* O1 = O0 + (size_t)8 * D_;
#pragma unroll
    for (int nt = 0; nt < 8; nt++) {
        int col = nt*8 + 2*tg;
        *(__half2*)(O0 + col) = __floats2half2_rn(ctx[nt][0]*inv0, ctx[nt][1]*inv0);
        *(__half2*)(O1 + col) = __floats2half2_rn(ctx[nt][2]*inv1, ctx[nt][3]*inv1);
    }
}

// smem geometry (halves)
#define A_ST   2048
#define BNT_ST 2048
#define BT_ST  2048

// ========== generic fp16 GEMM, BM=BN=128, BK=16, 4-stage cp.async ==========
template<int EPI, bool BTRANS, bool O32, bool O16>
__global__ void __launch_bounds__(256, 2)
gemm_h(const __half* __restrict__ A, const __half* __restrict__ Bm_,
       const float* __restrict__ bias, const float* __restrict__ res,
       float* __restrict__ C32, __half* __restrict__ C16,
       int M, int N, int K, int lda, int ldb, int ldc,
       long long aSB, long long aSH, long long bSB, long long bSH,
       long long cSB, long long cSH) {
    extern __shared__ __align__(16) __half sm[];
    constexpr int BSZ = BTRANS ? BT_ST : BNT_ST;
    __half* Asm = sm;
    __half* Bsm = sm + STAGES*A_ST;

    const int t = threadIdx.x, bm = blockIdx.y, bn = blockIdx.x, z = blockIdx.z;
    A   += (z / H_) * aSB + (z % H_) * aSH;
    Bm_ += (z / H_) * bSB + (z % H_) * bSH;
    long long cOff = (z / H_) * cSB + (z % H_) * cSH;
    const int lane = t & 31, wid = t >> 5;
    const int warpM = wid & 1, warpN = wid >> 1;
    const int g = lane >> 2, tg = lane & 3;

    const int ar = t >> 1, akc = t & 1;
    const int bkr = t >> 4, bcc = t & 15;
    const int aoff = swzA(ar, akc);
    const int boff = swzB(bkr, bcc);

    const __half* Ab0 = A + (size_t)(bm*128) * lda;

    auto issueA = [&](int s, int k0) {
        cp16(smem_u32(Asm + s*A_ST + aoff), Ab0 + (size_t)ar*lda + k0 + akc*8, true);
    };
    auto issueB = [&](int s, int k0) {
        __half* dst = Bsm + s*BSZ;
        if (!BTRANS) {
            bool p = (bn*128 + bcc*8) < N;
            cp16(smem_u32(dst + boff),
                 Bm_ + (size_t)(k0 + bkr)*ldb + bn*128 + bcc*8, p);
        } else {
            bool p = (bn*128 + ar) < N;
            cp16(smem_u32(dst + aoff),
                 Bm_ + (size_t)(bn*128 + ar)*ldb + k0 + akc*8, p);
        }
    };

    float acc[4][4][4];
#pragma unroll
    for (int i = 0; i < 4; i++)
#pragma unroll
        for (int j = 0; j < 4; j++)
#pragma unroll
            for (int c = 0; c < 4; c++) acc[i][j][c] = 0.f;

    const int l16 = lane & 15, lhi = lane >> 4;
    auto compute = [&](int s) {
        const __half* Ab = Asm + s*A_ST;
        const __half* Bb = Bsm + s*BSZ;
        uint32_t af[4][4], bf[4][2];
#pragma unroll
        for (int mt = 0; mt < 4; mt++) {
            int m0 = warpM*64 + mt*16;
            ldm_x4(af[mt], smem_u32(Ab + swzA(m0 + l16, lhi)));
        }
#pragma unroll
        for (int nt = 0; nt < 4; nt++) {
            int n0 = warpN*32 + nt*8;
            if (!BTRANS) ldm_x2t(bf[nt], smem_u32(Bb + swzB(l16, (n0 >> 3))));
            else         ldm_x2 (bf[nt], smem_u32(Bb + swzA(n0 + (l16 & 7), l16 >> 3)));
        }
#pragma unroll
        for (int mt = 0; mt < 4; mt++)
#pragma unroll
            for (int nt = 0; nt < 4; nt++) mma_h(acc[mt][nt], af[mt], bf[nt]);
    };

    const int nT = K >> 4;
#pragma unroll
    for (int s = 0; s < STAGES-1; s++) {
        if (s < nT) { issueA(s, s*16); issueB(s, s*16); }
        CP_COMMIT();
    }
    for (int ti = 0; ti < nT; ti++) {
        CP_WAIT(STAGES-2);
        __syncthreads();
        int nx = ti + STAGES - 1;
        if (nx < nT) { issueA(nx % STAGES, nx*16); issueB(nx % STAGES, nx*16); }
        CP_COMMIT();
        compute(ti % STAGES);
    }
#pragma unroll
    for (int mt = 0; mt < 4; mt++)
#pragma unroll
        for (int nt = 0; nt < 4; nt++) {
            int col = bn*128 + warpN*32 + nt*8 + 2*tg;
            if (col >= N) continue;
#pragma unroll
            for (int h = 0; h < 2; h++) {
                int row = bm*128 + warpM*64 + mt*16 + g + h*8;
                float v0 = acc[mt][nt][2*h], v1 = acc[mt][nt][2*h+1];
                if (EPI == 1 || EPI == 2 || EPI == 3) { v0 += bias[col]; v1 += bias[col+1]; }
                if (EPI == 2) { v0 = gelu_f(v0); v1 = gelu_f(v1); }
                if (EPI == 3) { size_t o = (size_t)row*ldc + col; v0 += res[o]; v1 += res[o+1]; }
                size_t o = cOff + (size_t)row*ldc + col;
                if (O32) *(float2*)(C32 + o) = make_float2(v0, v1);
                if (O16) *(__half2*)(C16 + o) = __floats2half2_rn(v0, v1);
            }
        }
}

// ========== split-K GEMM: partials[z] over K-slices ==========
__global__ void __launch_bounds__(256, 2)
gemm_splitk(const __half* __restrict__ A, const __half* __restrict__ Bm_,
            float* __restrict__ P, int Ks, int lda) {
    extern __shared__ __align__(16) __half sm[];
    __half* Asm = sm;
    __half* Bsm = sm + STAGES*A_ST;

    const int t = threadIdx.x, bm = blockIdx.y, bn = blockIdx.x, z = blockIdx.z;
    const int kbase = z * Ks;
    const int lane = t & 31, wid = t >> 5;
    const int warpM = wid & 1, warpN = wid >> 1;
    const int g = lane >> 2, tg = lane & 3;

    const int ar = t >> 1, akc = t & 1;
    const int bkr = t >> 4, bcc = t & 15;
    const int aoff = swzA(ar, akc);
    const int boff = swzB(bkr, bcc);

    const __half* Ab0 = A + (size_t)(bm*128) * lda + kbase;
    const __half* Bb0 = Bm_ + (size_t)kbase * D_;

    auto issueA = [&](int s, int k0) {
        cp16(smem_u32(Asm + s*A_ST + aoff), Ab0 + (size_t)ar*lda + k0 + akc*8, true);
    };
    auto issueB = [&](int s, int k0) {
        cp16(smem_u32(Bsm + s*BNT_ST + boff),
             Bb0 + (size_t)(k0 + bkr)*D_ + bn*128 + bcc*8, true);
    };

    float acc[4][4][4];
#pragma unroll
    for (int i = 0; i < 4; i++)
#pragma unroll
        for (int j = 0; j < 4; j++)
#pragma unroll
            for (int c = 0; c < 4; c++) acc[i][j][c] = 0.f;

    const int l16 = lane & 15, lhi = lane >> 4;
    auto compute = [&](int s) {
        const __half* Ab = Asm + s*A_ST;
        const __half* Bb = Bsm + s*BNT_ST;
        uint32_t af[4][4], bf[4][2];
#pragma unroll
        for (int mt = 0; mt < 4; mt++)
            ldm_x4(af[mt], smem_u32(Ab + swzA(warpM*64 + mt*16 + l16, lhi)));
#pragma unroll
        for (int nt = 0; nt < 4; nt++)
            ldm_x2t(bf[nt], smem_u32(Bb + swzB(l16, warpN*4 + nt)));
#pragma unroll
        for (int mt = 0; mt < 4; mt++)
#pragma unroll
            for (int nt = 0; nt < 4; nt++) mma_h(acc[mt][nt], af[mt], bf[nt]);
    };

    const int nT = Ks >> 4;
#pragma unroll
    for (int s = 0; s < STAGES-1; s++) {
        if (s < nT) { issueA(s, s*16); issueB(s, s*16); }
        CP_COMMIT();
    }
    for (int ti = 0; ti < nT; ti++) {
        CP_WAIT(STAGES-2);
        __syncthreads();
        int nx = ti + STAGES - 1;
        if (nx < nT) { issueA(nx % STAGES, nx*16); issueB(nx % STAGES, nx*16); }
        CP_COMMIT();
        compute(ti % STAGES);
    }
    float* Pz = P + (size_t)z * BS_ * D_;
#pragma unroll
    for (int mt = 0; mt < 4; mt++)
#pragma unroll
        for (int nt = 0; nt < 4; nt++) {
            int col = bn*128 + warpN*32 + nt*8 + 2*tg;
#pragma unroll
            for (int h = 0; h < 2; h++) {
                int row = bm*128 + warpM*64 + mt*16 + g + h*8;
                *(float2*)(Pz + (size_t)row*D_ + col) =
                    make_float2(acc[mt][nt][2*h], acc[mt][nt][2*h+1]);
            }
        }
}

// ---- combine 4 split-K partials + bias (+ residual) -> fp32/fp16 ----
template<bool O32, bool O16, bool RES>
__global__ void combine4(const float* __restrict__ P, const float* __restrict__ bias,
                         const float* __restrict__ res, float* __restrict__ o32,
                         __half* __restrict__ o16) {
    size_t i = ((size_t)blockIdx.x * 256 + threadIdx.x) * 2;
    const size_t MN = (size_t)BS_ * D_;
    float2 v0 = *(const float2*)(P + i);
    float2 v1 = *(const float2*)(P + MN + i);
    float2 v2 = *(const float2*)(P + 2*MN + i);
    float2 v3 = *(const float2*)(P + 3*MN + i);
    int col = (int)(i % D_);
    float a = v0.x + v1.x + v2.x + v3.x + bias[col];
    float b = v0.y + v1.y + v2.y + v3.y + bias[col + 1];
    if (RES) { a += res[i]; b += res[i + 1]; }
    if (O32) *(float2*)(o32 + i) = make_float2(a, b);
    if (O16) *(__half2*)(o16 + i) = __floats2half2_rn(a, b);
}

// ========== multi-output GEMM (QKV fused / A-Bm fused) ==========
struct MultiP {
    const __half* W[3];
    const float*  bias[3];
    float*        C32[3];
    __half*       C16[3];
};
__global__ void __launch_bounds__(256, 2)
gemm_multi(const __half* __restrict__ A, MultiP p, int nbnper, int K, int lda) {
    extern __shared__ __align__(16) __half sm[];
    __half* Asm = sm;
    __half* Bsm = sm + STAGES*A_ST;

    const int t = threadIdx.x, bm = blockIdx.y, bnG = blockIdx.x;
    const int sel = bnG / nbnper, bn = bnG % nbnper;
    const __half* W = p.W[sel];
    const float* bias = p.bias[sel];
    float* C32 = p.C32[sel];
    __half* C16 = p.C16[sel];

    const int lane = t & 31, wid = t >> 5;
    const int warpM = wid & 1, warpN = wid >> 1;
    const int g = lane >> 2, tg = lane & 3;
    const int ar = t >> 1, akc = t & 1;
    const int bkr = t >> 4, bcc = t & 15;
    const int aoff = swzA(ar, akc);
    const int boff = swzB(bkr, bcc);
    const __half* Ab0 = A + (size_t)(bm*128) * lda;

    auto issueA = [&](int s, int k0) {
        cp16(smem_u32(Asm + s*A_ST + aoff), Ab0 + (size_t)ar*lda + k0 + akc*8, true);
    };
    auto issueB = [&](int s, int k0) {
        cp16(smem_u32(Bsm + s*BNT_ST + boff),
             W + (size_t)(k0 + bkr)*D_ + bn*128 + bcc*8, true);
    };

    float acc[4][4][4];
#pragma unroll
    for (int i = 0; i < 4; i++)
#pragma unroll
        for (int j = 0; j < 4; j++)
#pragma unroll
            for (int c = 0; c < 4; c++) acc[i][j][c] = 0.f;

    const int l16 = lane & 15, lhi = lane >> 4;
    auto compute = [&](int s) {
        const __half* Ab = Asm + s*A_ST;
        const __half* Bb = Bsm + s*BNT_ST;
        uint32_t af[4][4], bf[4][2];
#pragma unroll
        for (int mt = 0; mt < 4; mt++)
            ldm_x4(af[mt], smem_u32(Ab + swzA(warpM*64 + mt*16 + l16, lhi)));
#pragma unroll
        for (int nt = 0; nt < 4; nt++)
            ldm_x2t(bf[nt], smem_u32(Bb + swzB(l16, warpN*4 + nt)));
#pragma unroll
        for (int mt = 0; mt < 4; mt++)
#pragma unroll
            for (int nt = 0; nt < 4; nt++) mma_h(acc[mt][nt], af[mt], bf[nt]);
    };

    const int nT = K >> 4;
#pragma unroll
    for (int s = 0; s < STAGES-1; s++) {
        if (s < nT) { issueA(s, s*16); issueB(s, s*16); }
        CP_COMMIT();
    }
    for (int ti = 0; ti < nT; ti++) {
        CP_WAIT(STAGES-2);
        __syncthreads();
        int nx = ti + STAGES - 1;
        if (nx < nT) { issueA(nx % STAGES, nx*16); issueB(nx % STAGES, nx*16); }
        CP_COMMIT();
        compute(ti % STAGES);
    }
#pragma unroll
    for (int mt = 0; mt < 4; mt++)
#pragma unroll
        for (int nt = 0; nt < 4; nt++) {
            int col = bn*128 + warpN*32 + nt*8 + 2*tg;
#pragma unroll
            for (int h = 0; h < 2; h++) {
                int row = bm*128 + warpM*64 + mt*16 + g + h*8;
                float v0 = acc[mt][nt][2*h], v1 = acc[mt][nt][2*h+1];
                if (bias) { v0 += bias[col]; v1 += bias[col+1]; }
                size_t o = (size_t)row*D_ + col;
                if (C32) *(float2*)(C32 + o) = make_float2(v0, v1);
                if (C16) *(__half2*)(C16 + o) = __floats2half2_rn(v0, v1);
            }
        }
}

// ---------------- row LayerNorm (width 768) -> fp16 out ----------------
__launch_bounds__(256)
__global__ void ln_kernel(const float* __restrict__ x, const float* __restrict__ g,
                          const float* __restrict__ b, __half* __restrict__ out) {
    const int r = blockIdx.x, t = threadIdx.x;
    __shared__ float rs[8], rq[8], stat[2];
    const float* row = x + (size_t)r * D_;
    float v0 = row[t], v1 = row[t + 256], v2 = row[t + 512];
    float s = v0 + v1 + v2;
    float q = v0*v0 + v1*v1 + v2*v2;
#pragma unroll
    for (int o = 16; o > 0; o >>= 1) {
        s += __shfl_xor_sync(0xffffffffu, s, o);
        q += __shfl_xor_sync(0xffffffffu, q, o);
    }
    if ((t & 31) == 0) { rs[t >> 5] = s; rq[t >> 5] = q; }
    __syncthreads();
    if (t == 0) {
        float S = 0.f, Q = 0.f;
        for (int w = 0; w < 8; w++) { S += rs[w]; Q += rq[w]; }
        float mean = S * (1.f/768.f);
        float var  = Q * (1.f/768.f) - mean*mean;
        stat[0] = mean; stat[1] = rsqrtf(var + 1e-5f);
    }
    __syncthreads();
    float mean = stat[0], rstd = stat[1];
    __half* o = out + (size_t)r * D_;
    o[t]       = __float2half((v0 - mean) * rstd * g[t]       + b[t]);
    o[t + 256] = __float2half((v1 - mean) * rstd * g[t + 256] + b[t + 256]);
    o[t + 512] = __float2half((v2 - mean) * rstd * g[t + 512] + b[t + 512]);
}

// ---- relreduce: warp-per-j-row LN + mean over j + residual + fused LN2 ----
__launch_bounds__(256)
__global__ void relreduce(const __half* __restrict__ Hp, const float* __restrict__ g,
                          const float* __restrict__ bln, const float* __restrict__ x1,
                          float* __restrict__ x2,
                          const float* __restrict__ ln2g, const float* __restrict__ ln2b,
                          __half* __restrict__ hout) {
    const int bci = blockIdx.x, t = threadIdx.x;
    const int w = t >> 5, lane = t & 31;
    __shared__ float smacc[8][768];
    __shared__ float rs[8], rq[8], stat[2];

    float acc[24];
#pragma unroll
    for (int e = 0; e < 24; e++) acc[e] = 0.f;

    const __half* base = Hp + (size_t)bci * 64 * D_;
    for (int jj = 0; jj < 8; jj++) {
        const __half2* row = (const __half2*)(base + (size_t)(w + jj*8) * D_);
        float v[24]; float s = 0.f, q = 0.f;
#pragma unroll
        for (int e = 0; e < 12; e++) {
            float2 f = __half22float2(row[lane + 32*e]);
            v[2*e] = f.x; v[2*e+1] = f.y;
            s += f.x + f.y; q += f.x*f.x + f.y*f.y;
        }
#pragma unroll
        for (int o = 16; o > 0; o >>= 1) {
            s += __shfl_xor_sync(0xffffffffu, s, o);
            q += __shfl_xor_sync(0xffffffffu, q, o);
        }
        float mean = s * (1.f/768.f);
        float rstd = rsqrtf(q * (1.f/768.f) - mean*mean + 1e-5f);
#pragma unroll
        for (int e = 0; e < 24; e++) acc[e] += (v[e] - mean) * rstd;
    }
#pragma unroll
    for (int e = 0; e < 12; e++) {
        smacc[w][2*(lane + 32*e)]     = acc[2*e];
        smacc[w][2*(lane + 32*e) + 1] = acc[2*e+1];
    }
    __syncthreads();

    float o0 = 0.f, o1 = 0.f, o2 = 0.f;
#pragma unroll
    for (int w8 = 0; w8 < 8; w8++) {
        o0 += smacc[w8][t];
        o1 += smacc[w8][t + 256];
        o2 += smacc[w8][t + 512];
    }
    size_t off = (size_t)bci * D_;
    o0 = x1[off + t]       + o0 * (1.f/64.f) * g[t]       + bln[t];
    o1 = x1[off + t + 256] + o1 * (1.f/64.f) * g[t + 256] + bln[t + 256];
    o2 = x1[off + t + 512] + o2 * (1.f/64.f) * g[t + 512] + bln[t + 512];
    x2[off + t] = o0; x2[off + t + 256] = o1; x2[off + t + 512] = o2;

    float s = o0 + o1 + o2, q = o0*o0 + o1*o1 + o2*o2;
#pragma unroll
    for (int o = 16; o > 0; o >>= 1) {
        s += __shfl_xor_sync(0xffffffffu, s, o);
        q += __shfl_xor_sync(0xffffffffu, q, o);
    }
    if (lane == 0) { rs[w] = s; rq[w] = q; }
    __syncthreads();
    if (t == 0) {
        float S = 0.f, Q = 0.f;
        for (int w8 = 0; w8 < 8; w8++) { S += rs[w8]; Q += rq[w8]; }
        float mean = S * (1.f/768.f);
        float var  = Q * (1.f/768.f) - mean*mean;
        stat[0] = mean; stat[1] = rsqrtf(var + 1e-5f);
    }
    __syncthreads();
    float mean = stat[0], rstd = stat[1];
    hout[off + t]       = __float2half((o0 - mean) * rstd * ln2g[t]       + ln2b[t]);
    hout[off + t + 256] = __float2half((o1 - mean) * rstd * ln2g[t + 256] + ln2b[t + 256]);
    hout[off + t + 512] = __float2half((o2 - mean) * rstd * ln2g[t + 512] + ln2b[t + 512]);
}

// ---------------- host orchestration ----------------
static float  *P_x1, *P_A, *P_Bm, *P_x2;
static __half *P_Hp, *P_G;
static __half *P_hh, *P_qh, *P_kh, *P_vh, *P_ctxh, *P_x1h, *P_fh;
static __half *P_Wqh, *P_Wkh, *P_Wvh, *P_Woh, *P_W1h, *P_W2h, *P_E1h, *P_E2h;
static bool g_init = false;

#define SM_NT  ((STAGES*A_ST + STAGES*BNT_ST)*2)   // 32768
#define SM_FL  ((FQ_ST + 4*FKV_ST)*2)              // 49152

extern "C" void kernel_launch(void* const* d_in, const int* in_sizes, int n_in,
                              void* d_out, int out_size) {
    if (!g_init) {
        cudaGetSymbolAddress((void**)&P_x1,  g_x1);
        cudaGetSymbolAddress((void**)&P_A,   g_A);
        cudaGetSymbolAddress((void**)&P_Bm,  g_Bm);
        cudaGetSymbolAddress((void**)&P_x2,  g_x2);
        cudaGetSymbolAddress((void**)&P_Hp,  g_Hp);
        cudaGetSymbolAddress((void**)&P_G,   g_G);
        cudaGetSymbolAddress((void**)&P_hh,  g_hh);
        cudaGetSymbolAddress((void**)&P_qh,  g_qh);
        cudaGetSymbolAddress((void**)&P_kh,  g_kh);
        cudaGetSymbolAddress((void**)&P_vh,  g_vh);
        cudaGetSymbolAddress((void**)&P_ctxh,g_ctxh);
        cudaGetSymbolAddress((void**)&P_x1h, g_x1h);
        cudaGetSymbolAddress((void**)&P_fh,  g_fh);
        cudaGetSymbolAddress((void**)&P_Wqh, g_Wqh);
        cudaGetSymbolAddress((void**)&P_Wkh, g_Wkh);
        cudaGetSymbolAddress((void**)&P_Wvh, g_Wvh);
        cudaGetSymbolAddress((void**)&P_Woh, g_Woh);
        cudaGetSymbolAddress((void**)&P_W1h, g_W1h);
        cudaGetSymbolAddress((void**)&P_W2h, g_W2h);
        cudaGetSymbolAddress((void**)&P_E1h, g_E1h);
        cudaGetSymbolAddress((void**)&P_E2h, g_E2h);
        cudaFuncSetAttribute(gemm_h<2,false,false,true>, cudaFuncAttributeMaxDynamicSharedMemorySize, SM_NT);
        cudaFuncSetAttribute(gemm_h<1,false,false,true>, cudaFuncAttributeMaxDynamicSharedMemorySize, SM_NT);
        cudaFuncSetAttribute(gemm_multi,  cudaFuncAttributeMaxDynamicSharedMemorySize, SM_NT);
        cudaFuncSetAttribute(gemm_splitk, cudaFuncAttributeMaxDynamicSharedMemorySize, SM_NT);
        cudaFuncSetAttribute(flash_attn,  cudaFuncAttributeMaxDynamicSharedMemorySize, SM_FL);
        g_init = true;
    }
    const float* x      = (const float*)d_in[0];
    const float* Wq     = (const float*)d_in[1];
    const float* bq     = (const float*)d_in[2];
    const float* Wk     = (const float*)d_in[3];
    const float* bk     = (const float*)d_in[4];
    const float* Wv     = (const float*)d_in[5];
    const float* bv     = (const float*)d_in[6];
    const float* Wo     = (const float*)d_in[7];
    const float* bo     = (const float*)d_in[8];
    const float* ln1_g  = (const float*)d_in[9];
    const float* ln1_b  = (const float*)d_in[10];
    const float* rel_W1 = (const float*)d_in[11];
    const float* rel_b1 = (const float*)d_in[12];
    const float* rel_W2 = (const float*)d_in[13];
    const float* rel_b2 = (const float*)d_in[14];
    const float* rel_ln_g = (const float*)d_in[15];
    const float* rel_ln_b = (const float*)d_in[16];
    const float* ln2_g  = (const float*)d_in[17];
    const float* ln2_b  = (const float*)d_in[18];
    const float* enc_W1 = (const float*)d_in[19];
    const float* enc_b1 = (const float*)d_in[20];
    const float* enc_W2 = (const float*)d_in[21];
    const float* enc_b2 = (const float*)d_in[22];
    float* out = (float*)d_out;

    const int DD = D_ * D_;
    float* PK = (float*)P_Hp;          // split-K scratch inside dead Hp buffer
    const int CGRID = BS_*D_/512;

    // 0) fused weight conversions
    {
        ConvP p;
        p.src[0]=Wq;    p.dst[0]=P_Wqh;
        p.src[1]=Wk;    p.dst[1]=P_Wkh;
        p.src[2]=Wv;    p.dst[2]=P_Wvh;
        p.src[3]=Wo;    p.dst[3]=P_Woh;
        p.src[4]=rel_W1;p.dst[4]=P_W1h;
        p.src[5]=rel_W2;p.dst[5]=P_W2h;
        p.src[6]=enc_W1;p.dst[6]=P_E1h;
        p.src[7]=enc_W2;p.dst[7]=P_E2h;
        int sz[8] = {DD, DD, DD, DD, 2*DD, DD, D_*DFF_, D_*DFF_};
        p.off[0] = 0;
        for (int k = 0; k < 8; k++) p.off[k+1] = p.off[k] + sz[k];
        int total = p.off[8];
        conv_all<<<(total/4 + 255)/256, 256>>>(p);
    }

    // 1) h = LN1(x) -> fp16
    ln_kernel<<<BS_, 256>>>(x, ln1_g, ln1_b, P_hh);
    // 2) fused QKV
    {
        MultiP p;
        p.W[0]=P_Wqh; p.W[1]=P_Wkh; p.W[2]=P_Wvh;
        p.bias[0]=bq; p.bias[1]=bk; p.bias[2]=bv;
        p.C32[0]=p.C32[1]=p.C32[2]=nullptr;
        p.C16[0]=P_qh; p.C16[1]=P_kh; p.C16[2]=P_vh;
        gemm_multi<<<dim3(18,16), 256, SM_NT>>>(P_hh, p, 6, D_, D_);
    }
    // 3) fused flash attention
    flash_attn<<<dim3(8, B_*H_), 256, SM_FL>>>(P_qh, P_kh, P_vh, P_ctxh);
    // 4) x1 = x + ctx@Wo + bo  (split-K=4)
    gemm_splitk<<<dim3(6,16,4), 256, SM_NT>>>(P_ctxh, P_Woh, PK, 192, D_);
    combine4<true,true,true><<<CGRID, 256>>>(PK, bo, x, P_x1, P_x1h);
    // 5) fused A / Bm (gemm_multi — proven best for this shape)
    {
        MultiP p;
        p.W[0]=P_W1h; p.W[1]=P_W1h + DD; p.W[2]=nullptr;
        p.bias[0]=rel_b1; p.bias[1]=nullptr; p.bias[2]=nullptr;
        p.C32[0]=P_A; p.C32[1]=P_Bm; p.C32[2]=nullptr;
        p.C16[0]=p.C16[1]=p.C16[2]=nullptr;
        gemm_multi<<<dim3(12,16), 256, SM_NT>>>(P_x1h, p, 6, D_, D_);
    }
    // 6) relation
    gelu_mat<<<dim3(2048, 2), 192>>>(P_A, P_Bm, P_G);
    gemm_h<1,false,false,true><<<dim3(6,1024), 256, SM_NT>>>(
        P_G, P_W2h, rel_b2, nullptr, nullptr, P_Hp,
        MREL, D_, D_, D_, D_, D_, 0,0,0,0,0,0);
    relreduce<<<BS_, 256>>>(P_Hp, rel_ln_g, rel_ln_b, P_x1, P_x2, ln2_g, ln2_b, P_hh);
    // 7) FFN: up-proj+gelu, then down-proj via split-K=4
    gemm_h<2,false,false,true><<<dim3(24,16), 256, SM_NT>>>(
        P_hh, P_E1h, enc_b1, nullptr, nullptr, P_fh,
        BS_, DFF_, D_, D_, DFF_, DFF_, 0,0,0,0,0,0);
    gemm_splitk<<<dim3(6,16,4), 256, SM_NT>>>(P_fh, P_E2h, PK, 768, DFF_);
    combine4<true,false,true><<<CGRID, 256>>>(PK, enc_b2, P_x2, out, nullptr);
}